// round 15
// baseline (speedup 1.0000x reference)
#include <cuda_runtime.h>
#include <cstdint>

#define D         64
#define EDGE_DIM  16
#define MSG_IN    144
#define UPD_IN    128
#define MAXN      50000
#define MAXE      800000

// ---------------- scratch (device globals; no allocation allowed) ----------------
__device__ __align__(256) float g_x[MAXN * D];
__device__ __align__(256) float g_P[MAXN * D];   // x @ W_i + msg_b  (dst side)
__device__ __align__(256) float g_Q[MAXN * D];   // x @ W_j          (src side)
__device__ __align__(256) float g_agg[MAXN * D];
__device__ int2 g_sd[MAXE];                      // (src, dst) packed
__device__ int g_is64;

typedef unsigned long long u64;

// ---------------- packed f32x2 helpers ----------------
__device__ __forceinline__ u64 pack2(float lo, float hi) {
    u64 r; asm("mov.b64 %0, {%1,%2};" : "=l"(r) : "f"(lo), "f"(hi)); return r;
}
__device__ __forceinline__ void fma2(u64& acc, u64 a, u64 b) {
    asm("fma.rn.f32x2 %0, %1, %2, %0;" : "+l"(acc) : "l"(a), "l"(b));
}
__device__ __forceinline__ u64 add2(u64 a, u64 b) {
    u64 r; asm("add.rn.f32x2 %0, %1, %2;" : "=l"(r) : "l"(a), "l"(b)); return r;
}
__device__ __forceinline__ void unpack2(u64 v, float& lo, float& hi) {
    asm("mov.b64 {%0,%1}, %2;" : "=f"(lo), "=f"(hi) : "l"(v));
}

// ---------------- dtype sniffing for edge_index ----------------
__global__ void detect_kernel(const unsigned int* __restrict__ idx) {
    __shared__ unsigned int acc[256];
    unsigned int v = 0;
    for (int i = threadIdx.x; i < 2048; i += 256) v |= idx[2 * i + 1];
    acc[threadIdx.x] = v;
    __syncthreads();
    for (int s = 128; s > 0; s >>= 1) {
        if (threadIdx.x < s) acc[threadIdx.x] |= acc[threadIdx.x + s];
        __syncthreads();
    }
    if (threadIdx.x == 0) g_is64 = (acc[0] == 0u) ? 1 : 0;
}

// ---------------- convert edge_index to packed int2 (src, dst) ----------------
__global__ void conv_idx_kernel(const void* __restrict__ eidx, int E) {
    int i = blockIdx.x * 256 + threadIdx.x;
    if (i >= E) return;
    int src, dst;
    if (g_is64) {
        const long long* p = reinterpret_cast<const long long*>(eidx);
        src = (int)p[i];
        dst = (int)p[(size_t)E + i];
    } else {
        const int* p = reinterpret_cast<const int*>(eidx);
        src = p[i];
        dst = p[E + i];
    }
    g_sd[i] = make_int2(src, dst);
}

// ---------------- P/Q precompute: persistent blocks, 1 thread/node, zeroes agg ----------------
__global__ void __launch_bounds__(256) pq_kernel(const float* __restrict__ xin,
                                                 const float* __restrict__ msg_w,
                                                 const float* __restrict__ msg_b,
                                                 int l, int N) {
    __shared__ __align__(16) float ws[64 * D];   // 16 KB
    __shared__ __align__(16) float bs[D];
    const int half = blockIdx.y;
    const float* x_src = xin ? xin : g_x;
    const float* W = msg_w + (size_t)l * MSG_IN * D + (size_t)half * 64 * D;
    for (int i = threadIdx.x; i < 64 * D; i += 256) ws[i] = W[i];
    if (threadIdx.x < D) bs[threadIdx.x] = half ? 0.f : msg_b[l * D + threadIdx.x];
    __syncthreads();

    const int stride = gridDim.x * 256;
    for (int v = blockIdx.x * 256 + threadIdx.x; v < N; v += stride) {
        if (half == 0) {   // zero agg row for this layer (edge kernel follows in-stream)
            float4 z = make_float4(0.f, 0.f, 0.f, 0.f);
            float4* ap = reinterpret_cast<float4*>(g_agg + (size_t)v * D);
#pragma unroll
            for (int j = 0; j < 16; j++) ap[j] = z;
        }

        u64 acc[32];
        const u64* bp = reinterpret_cast<const u64*>(bs);
#pragma unroll
        for (int j = 0; j < 32; j++) acc[j] = bp[j];

        const float4* xr = reinterpret_cast<const float4*>(x_src + (size_t)v * D);
        for (int k4 = 0; k4 < 16; k4++) {
            float4 xv = xr[k4];
#pragma unroll
            for (int c = 0; c < 4; c++) {
                float xs = (c == 0) ? xv.x : (c == 1) ? xv.y : (c == 2) ? xv.z : xv.w;
                u64 a = pack2(xs, xs);
                const ulonglong2* wr = reinterpret_cast<const ulonglong2*>(&ws[(k4 * 4 + c) * D]);
#pragma unroll
                for (int j4 = 0; j4 < 16; j4++) {
                    ulonglong2 w = wr[j4];
                    fma2(acc[2 * j4],     a, w.x);
                    fma2(acc[2 * j4 + 1], a, w.y);
                }
            }
        }
        float* out = (half ? g_Q : g_P) + (size_t)v * D;
        u64* o64 = reinterpret_cast<u64*>(out);
#pragma unroll
        for (int j = 0; j < 32; j++) o64[j] = acc[j];
    }
}

// ---------------- edge pass: warp-per-edge, uniform eattr loads, pipelined gathers ----------------
// agg[dst] += relu(P[dst] + Q[src] + ea @ W_e). Lane owns cols (2*lane, 2*lane+1).
// eattr read as 4 uniform float4 loads (warp broadcast, no shfl). P/Q gathers for
// the NEXT edge are issued before the current edge's compute+red.
#define EPW 16  // edges per warp
__global__ void __launch_bounds__(256) edge_kernel(const float* __restrict__ eattr,
                                                   const float* __restrict__ msg_w,
                                                   int l, int E) {
    const float* W = msg_w + (size_t)l * MSG_IN * D + (size_t)128 * D;
    const int lane = threadIdx.x & 31;
    const int gwarp = (blockIdx.x * 256 + threadIdx.x) >> 5;

    u64 Wreg[16];
#pragma unroll
    for (int k = 0; k < 16; k++)
        Wreg[k] = *reinterpret_cast<const u64*>(W + k * D + 2 * lane);

    const int e0 = gwarp * EPW;
    if (e0 >= E) return;
    const int eend = (e0 + EPW < E) ? e0 + EPW : E;

    // prologue: first edge's gathers
    int2 sd = g_sd[e0];
    u64 p = *reinterpret_cast<const u64*>(g_P + (size_t)sd.y * D + 2 * lane);
    u64 q = *reinterpret_cast<const u64*>(g_Q + (size_t)sd.x * D + 2 * lane);

    for (int e = e0; e < eend; e++) {
        // prefetch next edge's random gathers (long latency)
        int ndst = 0;
        u64 np = 0ULL, nq = 0ULL;
        if (e + 1 < eend) {
            int2 nsd = g_sd[e + 1];
            ndst = nsd.y;
            np = *reinterpret_cast<const u64*>(g_P + (size_t)nsd.y * D + 2 * lane);
            nq = *reinterpret_cast<const u64*>(g_Q + (size_t)nsd.x * D + 2 * lane);
        }

        // eattr: uniform (broadcast) loads, sequential across edges -> L1-resident
        const float4* ep = reinterpret_cast<const float4*>(eattr + (size_t)e * EDGE_DIM);
        float4 A = ep[0], B = ep[1], C = ep[2], Dv = ep[3];

        u64 m0 = add2(p, q);
        u64 m1 = 0ULL;
        fma2(m0, pack2(A.x, A.x), Wreg[0]);   fma2(m1, pack2(A.y, A.y), Wreg[1]);
        fma2(m0, pack2(A.z, A.z), Wreg[2]);   fma2(m1, pack2(A.w, A.w), Wreg[3]);
        fma2(m0, pack2(B.x, B.x), Wreg[4]);   fma2(m1, pack2(B.y, B.y), Wreg[5]);
        fma2(m0, pack2(B.z, B.z), Wreg[6]);   fma2(m1, pack2(B.w, B.w), Wreg[7]);
        fma2(m0, pack2(C.x, C.x), Wreg[8]);   fma2(m1, pack2(C.y, C.y), Wreg[9]);
        fma2(m0, pack2(C.z, C.z), Wreg[10]);  fma2(m1, pack2(C.w, C.w), Wreg[11]);
        fma2(m0, pack2(Dv.x, Dv.x), Wreg[12]); fma2(m1, pack2(Dv.y, Dv.y), Wreg[13]);
        fma2(m0, pack2(Dv.z, Dv.z), Wreg[14]); fma2(m1, pack2(Dv.w, Dv.w), Wreg[15]);
        m0 = add2(m0, m1);

        float lo, hi;
        unpack2(m0, lo, hi);
        lo = fmaxf(lo, 0.f);
        hi = fmaxf(hi, 0.f);
        // no "memory" clobber: keeps prefetched loads hoisted above the red
        asm volatile("red.global.add.v2.f32 [%0], {%1,%2};"
                     :: "l"(g_agg + (size_t)sd.y * D + 2 * lane), "f"(lo), "f"(hi));

        sd.y = ndst; p = np; q = nq;
    }
}

// ---------------- node update: persistent blocks (2/SM), 1 thread/node ----------------
__global__ void __launch_bounds__(256) upd_kernel(const float* __restrict__ xin,
                                                  const float* __restrict__ upd_w,
                                                  const float* __restrict__ upd_b,
                                                  int l, int N, float* __restrict__ xout) {
    __shared__ __align__(16) float ws[UPD_IN * D];   // 32 KB
    __shared__ __align__(16) float bs[D];
    const float* x_src = xin ? xin : g_x;
    float* x_dst = xout ? xout : g_x;
    const float* W = upd_w + (size_t)l * UPD_IN * D;
    for (int i = threadIdx.x; i < UPD_IN * D; i += 256) ws[i] = W[i];
    if (threadIdx.x < D) bs[threadIdx.x] = upd_b[l * D + threadIdx.x];
    __syncthreads();

    const int stride = gridDim.x * 256;
    for (int v = blockIdx.x * 256 + threadIdx.x; v < N; v += stride) {
        u64 acc[32];
        const u64* bp = reinterpret_cast<const u64*>(bs);
#pragma unroll
        for (int j = 0; j < 32; j++) acc[j] = bp[j];

        const float4* xr = reinterpret_cast<const float4*>(x_src + (size_t)v * D);
        const float4* ar = reinterpret_cast<const float4*>(g_agg + (size_t)v * D);

        for (int k4 = 0; k4 < 16; k4++) {
            float4 xv = xr[k4];
#pragma unroll
            for (int c = 0; c < 4; c++) {
                float xs = (c == 0) ? xv.x : (c == 1) ? xv.y : (c == 2) ? xv.z : xv.w;
                u64 a = pack2(xs, xs);
                const ulonglong2* wr = reinterpret_cast<const ulonglong2*>(&ws[(k4 * 4 + c) * D]);
#pragma unroll
                for (int j4 = 0; j4 < 16; j4++) {
                    ulonglong2 w = wr[j4];
                    fma2(acc[2 * j4],     a, w.x);
                    fma2(acc[2 * j4 + 1], a, w.y);
                }
            }
        }
        for (int k4 = 0; k4 < 16; k4++) {
            float4 av = ar[k4];
#pragma unroll
            for (int c = 0; c < 4; c++) {
                float xs = (c == 0) ? av.x : (c == 1) ? av.y : (c == 2) ? av.z : av.w;
                u64 a = pack2(xs, xs);
                const ulonglong2* wr = reinterpret_cast<const ulonglong2*>(&ws[(64 + k4 * 4 + c) * D]);
#pragma unroll
                for (int j4 = 0; j4 < 16; j4++) {
                    ulonglong2 w = wr[j4];
                    fma2(acc[2 * j4],     a, w.x);
                    fma2(acc[2 * j4 + 1], a, w.y);
                }
            }
        }

        float* o = x_dst + (size_t)v * D;
#pragma unroll
        for (int j = 0; j < 32; j++) {
            float lo, hi;
            unpack2(acc[j], lo, hi);
            float2 rv;
            rv.x = fmaxf(lo, 0.f);
            rv.y = fmaxf(hi, 0.f);
            *reinterpret_cast<float2*>(&o[2 * j]) = rv;
        }
    }
}

// ---------------- launcher ----------------
extern "C" void kernel_launch(void* const* d_in, const int* in_sizes, int n_in,
                              void* d_out, int out_size) {
    const float* x      = (const float*)d_in[0];
    const void*  eidx   = d_in[1];
    const float* eattr  = (const float*)d_in[2];
    const float* msg_w  = (const float*)d_in[3];
    const float* msg_b  = (const float*)d_in[4];
    const float* upd_w  = (const float*)d_in[5];
    const float* upd_b  = (const float*)d_in[6];

    const int N = in_sizes[0] / D;
    const int E = in_sizes[2] / EDGE_DIM;
    const int L = in_sizes[4] / D;

    detect_kernel<<<1, 256>>>((const unsigned int*)eidx);
    conv_idx_kernel<<<(E + 255) / 256, 256>>>(eidx, E);

    // Persistent node grids over 148 SMs.
    int pers = (N + 255) / 256;
    if (pers > 148) pers = 148;
    int pers_upd = (N + 255) / 256;
    if (pers_upd > 296) pers_upd = 296;          // 2 blocks/SM for upd
    const int edge_blocks = (E + 8 * EPW - 1) / (8 * EPW);

    for (int l = 0; l < L; l++) {
        const float* xin = (l == 0) ? x : nullptr;            // nullptr -> g_x
        float* xout = (l == L - 1) ? (float*)d_out : nullptr; // nullptr -> g_x

        dim3 pq_grid(pers, 2);
        pq_kernel<<<pq_grid, 256>>>(xin, msg_w, msg_b, l, N);
        edge_kernel<<<edge_blocks, 256>>>(eattr, msg_w, l, E);
        upd_kernel<<<pers_upd, 256>>>(xin, upd_w, upd_b, l, N, xout);
    }
}